// round 1
// baseline (speedup 1.0000x reference)
#include <cuda_runtime.h>
#include <cuda_bf16.h>
#include <math.h>

// Problem constants (MinGRUCell: B=8, T=4096, D=256, H=256)
#define BB 8
#define TT 4096
#define DD 256
#define HH 256
#define MM (BB * TT)          // 32768 rows

// GEMM tiling
#define BM 128
#define BN 128
#define BK 16
#define TM 8
#define TN 8

// Scratch for gate (post-sigmoid) and update, layout [M, H]
__device__ float g_scratch[(size_t)MM * HH];
__device__ float u_scratch[(size_t)MM * HH];

// ---------------------------------------------------------------------------
// Fused GEMM: computes Z = x @ Wz^T + bz (then sigmoid) and U = x @ Wh^T + bh.
// Treated as one logical GEMM with N=512 (cols 0..255 -> gate, 256..511 -> upd).
// blockIdx.x in [0,4): tiles of 128 cols; blockIdx.y: tiles of 128 rows.
// ---------------------------------------------------------------------------
__global__ __launch_bounds__(256, 2)
void mingru_gemm_kernel(const float* __restrict__ x,
                        const float* __restrict__ Wz,
                        const float* __restrict__ bz,
                        const float* __restrict__ Wh,
                        const float* __restrict__ bh)
{
    __shared__ float As[BK][BM + 4];
    __shared__ float Bs[BK][BN + 4];

    const int tid   = threadIdx.x;          // 0..255
    const int m0    = blockIdx.y * BM;
    const int ntile = blockIdx.x;            // 0..3
    const bool is_gate = (ntile < 2);
    const float* __restrict__ W    = is_gate ? Wz : Wh;
    const float* __restrict__ bias = is_gate ? bz : bh;
    const int h0col = (ntile & 1) * BN;       // col offset within H=256

    const int tx = tid & 15;                  // 0..15 (col group)
    const int ty = tid >> 4;                  // 0..15 (row group)

    float acc[TM][TN];
#pragma unroll
    for (int i = 0; i < TM; i++)
#pragma unroll
        for (int j = 0; j < TN; j++)
            acc[i][j] = 0.0f;

    // Loader mapping: tile is 128 rows x 16 cols = 512 float4; 2 per thread.
    const int l0row = tid >> 2;               // 0..63
    const int l0c4  = tid & 3;                // 0..3
    const int l1row = (tid + 256) >> 2;       // 64..127
    const int l1c4  = l0c4;

    for (int k0 = 0; k0 < DD; k0 += BK) {
        // global loads into registers
        float4 a0 = *reinterpret_cast<const float4*>(&x[(size_t)(m0 + l0row) * DD + k0 + l0c4 * 4]);
        float4 a1 = *reinterpret_cast<const float4*>(&x[(size_t)(m0 + l1row) * DD + k0 + l1c4 * 4]);
        float4 b0 = *reinterpret_cast<const float4*>(&W[(size_t)(h0col + l0row) * DD + k0 + l0c4 * 4]);
        float4 b1 = *reinterpret_cast<const float4*>(&W[(size_t)(h0col + l1row) * DD + k0 + l1c4 * 4]);

        __syncthreads();   // protect previous tile's reads

        // transpose into smem: As[k][m], Bs[k][n]
        As[l0c4 * 4 + 0][l0row] = a0.x;
        As[l0c4 * 4 + 1][l0row] = a0.y;
        As[l0c4 * 4 + 2][l0row] = a0.z;
        As[l0c4 * 4 + 3][l0row] = a0.w;
        As[l1c4 * 4 + 0][l1row] = a1.x;
        As[l1c4 * 4 + 1][l1row] = a1.y;
        As[l1c4 * 4 + 2][l1row] = a1.z;
        As[l1c4 * 4 + 3][l1row] = a1.w;

        Bs[l0c4 * 4 + 0][l0row] = b0.x;
        Bs[l0c4 * 4 + 1][l0row] = b0.y;
        Bs[l0c4 * 4 + 2][l0row] = b0.z;
        Bs[l0c4 * 4 + 3][l0row] = b0.w;
        Bs[l1c4 * 4 + 0][l1row] = b1.x;
        Bs[l1c4 * 4 + 1][l1row] = b1.y;
        Bs[l1c4 * 4 + 2][l1row] = b1.z;
        Bs[l1c4 * 4 + 3][l1row] = b1.w;

        __syncthreads();

#pragma unroll
        for (int kk = 0; kk < BK; kk++) {
            float a[TM], b[TN];
            float4 av0 = *reinterpret_cast<const float4*>(&As[kk][ty * TM]);
            float4 av1 = *reinterpret_cast<const float4*>(&As[kk][ty * TM + 4]);
            float4 bv0 = *reinterpret_cast<const float4*>(&Bs[kk][tx * TN]);
            float4 bv1 = *reinterpret_cast<const float4*>(&Bs[kk][tx * TN + 4]);
            a[0] = av0.x; a[1] = av0.y; a[2] = av0.z; a[3] = av0.w;
            a[4] = av1.x; a[5] = av1.y; a[6] = av1.z; a[7] = av1.w;
            b[0] = bv0.x; b[1] = bv0.y; b[2] = bv0.z; b[3] = bv0.w;
            b[4] = bv1.x; b[5] = bv1.y; b[6] = bv1.z; b[7] = bv1.w;
#pragma unroll
            for (int i = 0; i < TM; i++)
#pragma unroll
                for (int j = 0; j < TN; j++)
                    acc[i][j] = fmaf(a[i], b[j], acc[i][j]);
        }
    }

    // Epilogue: bias (+ sigmoid for gate), write to scratch [M, H]
#pragma unroll
    for (int i = 0; i < TM; i++) {
        const int m = m0 + ty * TM + i;
        float* dst = (is_gate ? g_scratch : u_scratch) + (size_t)m * HH;
#pragma unroll
        for (int j = 0; j < TN; j++) {
            const int n = h0col + tx * TN + j;
            float v = acc[i][j] + bias[n];
            if (is_gate) {
                v = 1.0f / (1.0f + expf(-v));
            }
            dst[n] = v;
        }
    }
}

// ---------------------------------------------------------------------------
// Sequential scan over T, parallel over (b, h). One thread per (b,h) lane.
// h_{t} = (1-g_t) h_{t-1} + g_t u_t  ==  h += g_t * (u_t - h)
// ---------------------------------------------------------------------------
__global__ void mingru_scan_kernel(const float* __restrict__ h0,
                                   float* __restrict__ out)
{
    const int idx = blockIdx.x * blockDim.x + threadIdx.x;   // 0..2047
    if (idx >= BB * HH) return;
    const int b  = idx >> 8;      // /256
    const int hh = idx & (HH - 1);

    float h = h0[b * HH + hh];
    const size_t base = (size_t)b * TT * HH + hh;
    const float* __restrict__ gp = g_scratch + base;
    const float* __restrict__ up = u_scratch + base;
    float* __restrict__ op = out + base;

#pragma unroll 4
    for (int t = 0; t < TT; t++) {
        const size_t off = (size_t)t * HH;
        float g = gp[off];
        float u = up[off];
        h = fmaf(g, u - h, h);
        op[off] = h;
    }
}

extern "C" void kernel_launch(void* const* d_in, const int* in_sizes, int n_in,
                              void* d_out, int out_size)
{
    const float* x  = (const float*)d_in[0];   // [B,T,D]
    const float* h0 = (const float*)d_in[1];   // [B,H]
    const float* Wz = (const float*)d_in[2];   // [H,D]
    const float* bz = (const float*)d_in[3];   // [H]
    const float* Wh = (const float*)d_in[4];   // [H,D]
    const float* bh = (const float*)d_in[5];   // [H]
    float* out = (float*)d_out;                // [B,T,H]

    dim3 grid(4, MM / BM);      // 4 col tiles (N=512 logical), 256 row tiles
    mingru_gemm_kernel<<<grid, 256>>>(x, Wz, bz, Wh, bh);

    mingru_scan_kernel<<<16, 128>>>(h0, out);
}

// round 2
// speedup vs baseline: 3.0346x; 3.0346x over previous
#include <cuda_runtime.h>
#include <cuda_bf16.h>
#include <math.h>

// Problem constants (MinGRUCell: B=8, T=4096, D=256, H=256)
#define BB 8
#define TT 4096
#define DD 256
#define HH 256
#define MM (BB * TT)          // 32768 rows

// Chunked scan config
#define NCH 64                // chunks per sequence
#define CLEN 64               // steps per chunk (NCH*CLEN == TT)

// GEMM tiling
#define BM 128
#define BN 128
#define BK 16
#define TM 8
#define TN 8

// Scratch: gate (post-sigmoid) and update, layout [B*T, H]
__device__ float g_scratch[(size_t)MM * HH];
__device__ float u_scratch[(size_t)MM * HH];
// Chunk summaries / chunk-start states, layout [B*NCH, H]
__device__ float chunkA[(size_t)BB * NCH * HH];
__device__ float chunkB[(size_t)BB * NCH * HH];
__device__ float hstart[(size_t)BB * NCH * HH];

// ---------------------------------------------------------------------------
// Fused GEMM: Z = sigmoid(x @ Wz^T + bz), U = x @ Wh^T + bh.
// Logical GEMM with N=512 (cols 0..255 -> gate, 256..511 -> update).
// ---------------------------------------------------------------------------
__global__ __launch_bounds__(256, 2)
void mingru_gemm_kernel(const float* __restrict__ x,
                        const float* __restrict__ Wz,
                        const float* __restrict__ bz,
                        const float* __restrict__ Wh,
                        const float* __restrict__ bh)
{
    __shared__ float As[BK][BM + 4];
    __shared__ float Bs[BK][BN + 4];

    const int tid   = threadIdx.x;          // 0..255
    const int m0    = blockIdx.y * BM;
    const int ntile = blockIdx.x;            // 0..3
    const bool is_gate = (ntile < 2);
    const float* __restrict__ W    = is_gate ? Wz : Wh;
    const float* __restrict__ bias = is_gate ? bz : bh;
    const int h0col = (ntile & 1) * BN;

    const int tx = tid & 15;
    const int ty = tid >> 4;

    float acc[TM][TN];
#pragma unroll
    for (int i = 0; i < TM; i++)
#pragma unroll
        for (int j = 0; j < TN; j++)
            acc[i][j] = 0.0f;

    const int l0row = tid >> 2;
    const int l0c4  = tid & 3;
    const int l1row = (tid + 256) >> 2;
    const int l1c4  = l0c4;

    for (int k0 = 0; k0 < DD; k0 += BK) {
        float4 a0 = *reinterpret_cast<const float4*>(&x[(size_t)(m0 + l0row) * DD + k0 + l0c4 * 4]);
        float4 a1 = *reinterpret_cast<const float4*>(&x[(size_t)(m0 + l1row) * DD + k0 + l1c4 * 4]);
        float4 b0 = *reinterpret_cast<const float4*>(&W[(size_t)(h0col + l0row) * DD + k0 + l0c4 * 4]);
        float4 b1 = *reinterpret_cast<const float4*>(&W[(size_t)(h0col + l1row) * DD + k0 + l1c4 * 4]);

        __syncthreads();

        As[l0c4 * 4 + 0][l0row] = a0.x;
        As[l0c4 * 4 + 1][l0row] = a0.y;
        As[l0c4 * 4 + 2][l0row] = a0.z;
        As[l0c4 * 4 + 3][l0row] = a0.w;
        As[l1c4 * 4 + 0][l1row] = a1.x;
        As[l1c4 * 4 + 1][l1row] = a1.y;
        As[l1c4 * 4 + 2][l1row] = a1.z;
        As[l1c4 * 4 + 3][l1row] = a1.w;

        Bs[l0c4 * 4 + 0][l0row] = b0.x;
        Bs[l0c4 * 4 + 1][l0row] = b0.y;
        Bs[l0c4 * 4 + 2][l0row] = b0.z;
        Bs[l0c4 * 4 + 3][l0row] = b0.w;
        Bs[l1c4 * 4 + 0][l1row] = b1.x;
        Bs[l1c4 * 4 + 1][l1row] = b1.y;
        Bs[l1c4 * 4 + 2][l1row] = b1.z;
        Bs[l1c4 * 4 + 3][l1row] = b1.w;

        __syncthreads();

#pragma unroll
        for (int kk = 0; kk < BK; kk++) {
            float a[TM], b[TN];
            float4 av0 = *reinterpret_cast<const float4*>(&As[kk][ty * TM]);
            float4 av1 = *reinterpret_cast<const float4*>(&As[kk][ty * TM + 4]);
            float4 bv0 = *reinterpret_cast<const float4*>(&Bs[kk][tx * TN]);
            float4 bv1 = *reinterpret_cast<const float4*>(&Bs[kk][tx * TN + 4]);
            a[0] = av0.x; a[1] = av0.y; a[2] = av0.z; a[3] = av0.w;
            a[4] = av1.x; a[5] = av1.y; a[6] = av1.z; a[7] = av1.w;
            b[0] = bv0.x; b[1] = bv0.y; b[2] = bv0.z; b[3] = bv0.w;
            b[4] = bv1.x; b[5] = bv1.y; b[6] = bv1.z; b[7] = bv1.w;
#pragma unroll
            for (int i = 0; i < TM; i++)
#pragma unroll
                for (int j = 0; j < TN; j++)
                    acc[i][j] = fmaf(a[i], b[j], acc[i][j]);
        }
    }

#pragma unroll
    for (int i = 0; i < TM; i++) {
        const int m = m0 + ty * TM + i;
        float* dst = (is_gate ? g_scratch : u_scratch) + (size_t)m * HH;
#pragma unroll
        for (int j = 0; j < TN; j++) {
            const int n = h0col + tx * TN + j;
            float v = acc[i][j] + bias[n];
            if (is_gate) {
                v = 1.0f / (1.0f + expf(-v));
            }
            dst[n] = v;
        }
    }
}

// ---------------------------------------------------------------------------
// Scan pass 1: per (b, chunk, h), compose the 64 affine steps into (A, B):
//   h_out = A * h_in + B  where step is h' = (1-g) h + g u.
// idx = ((b * NCH + c) * HH + h); h fastest -> coalesced.
// ---------------------------------------------------------------------------
__global__ __launch_bounds__(256)
void mingru_scan_pass1(void)
{
    const int idx = blockIdx.x * blockDim.x + threadIdx.x;
    const int h = idx & (HH - 1);
    const int c = (idx >> 8) & (NCH - 1);
    const int b = idx >> 14;

    const size_t base = ((size_t)b * TT + (size_t)c * CLEN) * HH + h;
    const float* __restrict__ gp = g_scratch + base;
    const float* __restrict__ up = u_scratch + base;

    float A = 1.0f, Bv = 0.0f;
#pragma unroll 8
    for (int t = 0; t < CLEN; t++) {
        const size_t off = (size_t)t * HH;
        float g = gp[off];
        float u = up[off];
        float a = 1.0f - g;
        Bv = fmaf(a, Bv, g * u);   // B' = a*B + g*u
        A  = A * a;                 // A' = a*A
    }
    chunkA[idx] = A;
    chunkB[idx] = Bv;
}

// ---------------------------------------------------------------------------
// Scan pass 2: carry h0 across chunk summaries. One thread per (b, h).
// Stores chunk-start hidden state for every chunk.
// ---------------------------------------------------------------------------
__global__ __launch_bounds__(256)
void mingru_scan_pass2(const float* __restrict__ h0)
{
    const int idx = blockIdx.x * blockDim.x + threadIdx.x;  // 0..2047
    const int h = idx & (HH - 1);
    const int b = idx >> 8;

    float hc = h0[b * HH + h];
#pragma unroll 8
    for (int c = 0; c < NCH; c++) {
        const size_t ci = ((size_t)b * NCH + c) * HH + h;
        hstart[ci] = hc;
        hc = fmaf(chunkA[ci], hc, chunkB[ci]);
    }
}

// ---------------------------------------------------------------------------
// Scan pass 3: replay each chunk from its start state, writing outputs.
// ---------------------------------------------------------------------------
__global__ __launch_bounds__(256)
void mingru_scan_pass3(float* __restrict__ out)
{
    const int idx = blockIdx.x * blockDim.x + threadIdx.x;
    const int h = idx & (HH - 1);
    const int c = (idx >> 8) & (NCH - 1);
    const int b = idx >> 14;

    const size_t base = ((size_t)b * TT + (size_t)c * CLEN) * HH + h;
    const float* __restrict__ gp = g_scratch + base;
    const float* __restrict__ up = u_scratch + base;
    float* __restrict__ op = out + base;

    float hc = hstart[idx];
#pragma unroll 8
    for (int t = 0; t < CLEN; t++) {
        const size_t off = (size_t)t * HH;
        float g = gp[off];
        float u = up[off];
        hc = fmaf(g, u - hc, hc);   // h' = (1-g)h + g u
        op[off] = hc;
    }
}

extern "C" void kernel_launch(void* const* d_in, const int* in_sizes, int n_in,
                              void* d_out, int out_size)
{
    const float* x  = (const float*)d_in[0];   // [B,T,D]
    const float* h0 = (const float*)d_in[1];   // [B,H]
    const float* Wz = (const float*)d_in[2];   // [H,D]
    const float* bz = (const float*)d_in[3];   // [H]
    const float* Wh = (const float*)d_in[4];   // [H,D]
    const float* bh = (const float*)d_in[5];   // [H]
    float* out = (float*)d_out;                // [B,T,H]

    dim3 grid(4, MM / BM);
    mingru_gemm_kernel<<<grid, 256>>>(x, Wz, bz, Wh, bh);

    const int scan_threads = BB * NCH * HH;    // 131072
    mingru_scan_pass1<<<scan_threads / 256, 256>>>();
    mingru_scan_pass2<<<BB * HH / 256, 256>>>(h0);
    mingru_scan_pass3<<<scan_threads / 256, 256>>>(out);
}

// round 4
// speedup vs baseline: 3.3484x; 1.1034x over previous
#include <cuda_runtime.h>
#include <cuda_bf16.h>
#include <math.h>
#include <stdint.h>

// Problem constants (MinGRUCell: B=8, T=4096, D=256, H=256)
#define BB 8
#define TT 4096
#define DD 256
#define HH 256
#define MM (BB * TT)          // 32768 rows
#define NN 512                // logical N: gate(256) + update(256)

// Chunked scan config
#define NCH 64
#define CLEN 64

// tcgen05 only exists in the arch-specific (sm_103a) compilation pass.
#if defined(__CUDA_ARCH_FEAT_SM103_ALL) || defined(__CUDA_ARCH_FEAT_SM100_ALL) || defined(__CUDA_ARCH_FEAT_SM101_ALL)
#define HAS_TCGEN05 1
#else
#define HAS_TCGEN05 0
#endif

// Scratch
__device__ float g_scratch[(size_t)MM * HH];
__device__ float u_scratch[(size_t)MM * HH];
__device__ float chunkA[(size_t)BB * NCH * HH];
__device__ float chunkB[(size_t)BB * NCH * HH];
__device__ float hstart[(size_t)BB * NCH * HH];
// Pre-split weights: rows 0..255 = Wz, 256..511 = Wh   [NN, DD] bf16
__device__ __nv_bfloat16 Wcat_hi[(size_t)NN * DD];
__device__ __nv_bfloat16 Wcat_lo[(size_t)NN * DD];

// ---------------------------------------------------------------------------
// PTX helpers
// ---------------------------------------------------------------------------
__device__ __forceinline__ uint32_t smem_u32(const void* p) {
    uint32_t a;
    asm("{ .reg .u64 t; cvta.to.shared.u64 t, %1; cvt.u32.u64 %0, t; }"
        : "=r"(a) : "l"(p));
    return a;
}

#define SW128(o) ((o) ^ (((o) >> 3) & 0x70))

static constexpr uint64_t SMEM_DESC_BASE_SW128_C =
    (uint64_t(2)  << 61) | (uint64_t(1) << 46) | (uint64_t(64) << 32) | (uint64_t(1) << 16);
#define MK_DESC(addr) (SMEM_DESC_BASE_SW128_C | ((uint64_t)((addr) >> 4) & 0x3FFF))

#if HAS_TCGEN05
#define TC_ALLOC(sm, n)  asm volatile("tcgen05.alloc.cta_group::1.sync.aligned.shared::cta.b32 [%0], %1;" :: "r"((uint32_t)(sm)), "r"((uint32_t)(n)) : "memory")
#define TC_DEALLOC(t, n) asm volatile("tcgen05.dealloc.cta_group::1.sync.aligned.b32 %0, %1;" :: "r"(t), "r"((uint32_t)(n)))
#define TC_RELINQ()      asm volatile("tcgen05.relinquish_alloc_permit.cta_group::1.sync.aligned;")
#define TC_COMMIT(mb)    asm volatile("tcgen05.commit.cta_group::1.mbarrier::arrive::one.shared::cluster.b64 [%0];" :: "r"((uint32_t)(mb)) : "memory")
#define TC_WAIT_LD()     asm volatile("tcgen05.wait::ld.sync.aligned;" ::: "memory")
#define TC_FENCE_AFTER() asm volatile("tcgen05.fence::after_thread_sync;" ::: "memory")
#define TC_FENCE_BEFORE() asm volatile("tcgen05.fence::before_thread_sync;" ::: "memory")
#define FENCE_ASYNC()    asm volatile("fence.proxy.async.shared::cta;" ::: "memory")
#define MBAR_INIT(mb, c) asm volatile("mbarrier.init.shared.b64 [%0], %1;" :: "r"((uint32_t)(mb)), "r"((uint32_t)(c)) : "memory")

#define MBAR_WAIT(mb, ph) do {                                                 \
    uint32_t _m = (uint32_t)(mb), _p = (uint32_t)(ph), _d;                     \
    asm volatile("{\n\t.reg .pred p;\n\t"                                      \
        "mbarrier.try_wait.parity.acquire.cta.shared::cta.b64 p, [%1], %2;\n\t"\
        "selp.b32 %0, 1, 0, p;\n\t}"                                           \
        : "=r"(_d) : "r"(_m), "r"(_p) : "memory");                             \
    if (!_d) {                                                                 \
        asm volatile("{\n\t.reg .pred P1;\n\t"                                 \
            "WL_%=:\n\t"                                                       \
            "mbarrier.try_wait.parity.acquire.cta.shared::cta.b64 P1, [%0], %1, 0x989680;\n\t" \
            "@P1 bra.uni WD_%=;\n\t"                                           \
            "bra.uni WL_%=;\n\t"                                               \
            "WD_%=:\n\t}"                                                      \
            :: "r"(_m), "r"(_p) : "memory");                                   \
    }                                                                          \
} while (0)

#define LDTM32(r, ta)                                                          \
    asm volatile("tcgen05.ld.sync.aligned.32x32b.x32.b32 "                     \
        "{%0,%1,%2,%3,%4,%5,%6,%7,%8,%9,%10,%11,%12,%13,%14,%15,"              \
        "%16,%17,%18,%19,%20,%21,%22,%23,%24,%25,%26,%27,%28,%29,%30,%31}, [%32];" \
        : "=r"((r)[0]),"=r"((r)[1]),"=r"((r)[2]),"=r"((r)[3]),                 \
          "=r"((r)[4]),"=r"((r)[5]),"=r"((r)[6]),"=r"((r)[7]),                 \
          "=r"((r)[8]),"=r"((r)[9]),"=r"((r)[10]),"=r"((r)[11]),               \
          "=r"((r)[12]),"=r"((r)[13]),"=r"((r)[14]),"=r"((r)[15]),             \
          "=r"((r)[16]),"=r"((r)[17]),"=r"((r)[18]),"=r"((r)[19]),             \
          "=r"((r)[20]),"=r"((r)[21]),"=r"((r)[22]),"=r"((r)[23]),             \
          "=r"((r)[24]),"=r"((r)[25]),"=r"((r)[26]),"=r"((r)[27]),             \
          "=r"((r)[28]),"=r"((r)[29]),"=r"((r)[30]),"=r"((r)[31])              \
        : "r"(ta))

__device__ __forceinline__ void mma_f16_ss(uint32_t d, uint64_t a, uint64_t b,
                                           uint32_t idesc, uint32_t en) {
    asm volatile(
        "{\n\t.reg .pred p;\n\tsetp.ne.u32 p, %5, 0;\n\t"
        "tcgen05.mma.cta_group::1.kind::f16 [%0], %1, %2, %3, {%4, %4, %4, %4}, p;\n\t}"
        :: "r"(d), "l"(a), "l"(b), "r"(idesc), "r"(0u), "r"(en) : "memory");
}
#endif // HAS_TCGEN05

// idesc: dtype=F32, atype=BF16, btype=BF16, N=256, M=128
static constexpr uint32_t GEMM_IDESC =
    (1u << 4) | (1u << 7) | (1u << 10) | ((256u / 8) << 17) | ((128u / 16) << 24);

// ---------------------------------------------------------------------------
// Weight pre-split: Wcat_{hi,lo} = split(concat(Wz, Wh))
// ---------------------------------------------------------------------------
__global__ __launch_bounds__(256)
void mingru_wprep_kernel(const float* __restrict__ Wz, const float* __restrict__ Wh)
{
    const int i = blockIdx.x * 256 + threadIdx.x;   // 0 .. NN*DD-1
    const int n = i >> 8;
    const int d = i & 255;
    float v = (n < HH) ? Wz[n * DD + d] : Wh[(n - HH) * DD + d];
    __nv_bfloat16 hi = __float2bfloat16(v);
    Wcat_hi[i] = hi;
    Wcat_lo[i] = __float2bfloat16(v - __bfloat162float(hi));
}

// ---------------------------------------------------------------------------
// tcgen05 GEMM: per CTA M=128, N=256 (gate or update), K=256 in 4 chunks of 64.
// 3-product bf16 split accumulated in fp32 TMEM.
// grid = (2, 256): x = gate/update, y = M tile. 128 threads.
// ---------------------------------------------------------------------------
#define KCH 64                 // K per chunk (= 128 bytes bf16 = SW128 atom row)
#define NKC (DD / KCH)         // 4 chunks
#define A_HI_OFF  1024
#define A_LO_OFF  (A_HI_OFF + 128 * 128)        // 17408
#define B_HI_OFF  (A_LO_OFF + 128 * 128)        // 33792
#define B_LO_OFF  (B_HI_OFF + 256 * 128)        // 66560
#define SMEM_END  (B_LO_OFF + 256 * 128)        // 99328
#define STAGE_OFF 1024                          // reuse A area in epilogue
#define STAGE_S   129                           // padded col stride (floats)
#define GEMM_SMEM (SMEM_END + 1024)             // + alignment slack

__global__ __launch_bounds__(128, 2)
void mingru_gemm_tc(const float* __restrict__ x,
                    const float* __restrict__ bz,
                    const float* __restrict__ bh)
{
#if HAS_TCGEN05
    extern __shared__ char smem_raw[];
    char* smem = (char*)(((uintptr_t)smem_raw + 1023) & ~(uintptr_t)1023);
    const uint32_t sbase = smem_u32(smem);

    const int tid = threadIdx.x;          // 0..127
    const int wid = tid >> 5;
    const int lid = tid & 31;
    const int m0 = blockIdx.y * 128;
    const bool is_gate = (blockIdx.x == 0);
    const int n0 = blockIdx.x * 256;      // row offset into Wcat
    const float* __restrict__ bias = is_gate ? bz : bh;
    float* __restrict__ outbuf = is_gate ? g_scratch : u_scratch;

    // --- TMEM alloc (256 cols fp32 for D) ---
    if (wid == 0) TC_ALLOC(sbase + 0, 256);
    if (tid == 0) MBAR_INIT(sbase + 8, 1);
    __syncthreads();
    uint32_t tmem;
    asm volatile("ld.shared.b32 %0, [%1];" : "=r"(tmem) : "r"(sbase + 0));

    const uint64_t adesc_hi = MK_DESC(sbase + A_HI_OFF);
    const uint64_t adesc_lo = MK_DESC(sbase + A_LO_OFF);
    const uint64_t bdesc_hi = MK_DESC(sbase + B_HI_OFF);
    const uint64_t bdesc_lo = MK_DESC(sbase + B_LO_OFF);

    bool first = true;
    for (int kc = 0; kc < NKC; kc++) {
        const int k0 = kc * KCH;

        // ---- Load + split A chunk: 128 rows x 64 cols fp32 -> bf16 hi/lo ----
#pragma unroll
        for (int i = 0; i < 16; i++) {
            const int idx = i * 128 + tid;       // 0..2047
            const int row = idx >> 4;            // 0..127
            const int c4  = idx & 15;            // float4 index within row
            float4 v = *reinterpret_cast<const float4*>(
                &x[(size_t)(m0 + row) * DD + k0 + c4 * 4]);
            __nv_bfloat16 h0 = __float2bfloat16(v.x);
            __nv_bfloat16 h1 = __float2bfloat16(v.y);
            __nv_bfloat16 h2 = __float2bfloat16(v.z);
            __nv_bfloat16 h3 = __float2bfloat16(v.w);
            __nv_bfloat162 hp0 = __nv_bfloat162(h0, h1);
            __nv_bfloat162 hp1 = __nv_bfloat162(h2, h3);
            __nv_bfloat162 lp0 = __nv_bfloat162(
                __float2bfloat16(v.x - __bfloat162float(h0)),
                __float2bfloat16(v.y - __bfloat162float(h1)));
            __nv_bfloat162 lp1 = __nv_bfloat162(
                __float2bfloat16(v.z - __bfloat162float(h2)),
                __float2bfloat16(v.w - __bfloat162float(h3)));
            uint32_t off = SW128((uint32_t)(row * 128 + c4 * 8));
            uint2 hw = make_uint2(*(uint32_t*)&hp0, *(uint32_t*)&hp1);
            uint2 lw = make_uint2(*(uint32_t*)&lp0, *(uint32_t*)&lp1);
            *reinterpret_cast<uint2*>(smem + A_HI_OFF + off) = hw;
            *reinterpret_cast<uint2*>(smem + A_LO_OFF + off) = lw;
        }

        // ---- Load B chunk (pre-split bf16): 256 rows x 64 cols ----
#pragma unroll
        for (int i = 0; i < 16; i++) {
            const int idx = i * 128 + tid;       // 0..2047
            const int row = idx >> 3;            // 0..255
            const int c16 = idx & 7;             // 16B unit within row
            const size_t src = (size_t)(n0 + row) * DD + k0 + c16 * 8;
            uint4 bh16 = *reinterpret_cast<const uint4*>(&Wcat_hi[src]);
            uint4 bl16 = *reinterpret_cast<const uint4*>(&Wcat_lo[src]);
            uint32_t off = SW128((uint32_t)(row * 128 + c16 * 16));
            *reinterpret_cast<uint4*>(smem + B_HI_OFF + off) = bh16;
            *reinterpret_cast<uint4*>(smem + B_LO_OFF + off) = bl16;
        }
        __syncthreads();

        // ---- Issue 12 MMAs: 3 splits x 4 K-steps of 16 ----
        if (tid == 0) {
            FENCE_ASYNC();
            const uint64_t ad[3] = { adesc_hi, adesc_lo, adesc_hi };
            const uint64_t bd[3] = { bdesc_hi, bdesc_hi, bdesc_lo };
#pragma unroll
            for (int p = 0; p < 3; p++) {
#pragma unroll
                for (int ks = 0; ks < 4; ks++) {
                    mma_f16_ss(tmem, ad[p] + ks * 2, bd[p] + ks * 2,
                               GEMM_IDESC, first ? 0u : 1u);
                    first = false;
                }
            }
            TC_COMMIT(sbase + 8);
        }
        MBAR_WAIT(sbase + 8, kc & 1);
        __syncthreads();
    }
    TC_FENCE_AFTER();

    // ---- Epilogue: 4 blocks of 64 cols; bias (+sigmoid), SMEM transpose ----
    float* stage = reinterpret_cast<float*>(smem + STAGE_OFF);
    const int row = wid * 32 + lid;
    for (int cb = 0; cb < 4; cb++) {
        uint32_t r[64];
        LDTM32(r, tmem + cb * 64);
        LDTM32(r + 32, tmem + cb * 64 + 32);
        TC_WAIT_LD();
        TC_FENCE_BEFORE();
#pragma unroll
        for (int j = 0; j < 64; j++) {
            float v = __uint_as_float(r[j]) + __ldg(&bias[cb * 64 + j]);
            if (is_gate) v = 1.0f / (1.0f + __expf(-v));
            stage[j * STAGE_S + row] = v;
        }
        __syncthreads();
        // coalesced copy out: 128 rows x 64 cols
        const int col = tid & 63;
        const int rh = tid >> 6;
#pragma unroll 8
        for (int rr = 0; rr < 64; rr++) {
            const int r2 = rr * 2 + rh;
            outbuf[(size_t)(m0 + r2) * HH + cb * 64 + col] =
                stage[col * STAGE_S + r2];
        }
        __syncthreads();
    }

    if (wid == 0) {
        TC_RELINQ();
        TC_DEALLOC(tmem, 256);
    }
#endif // HAS_TCGEN05
}

// ---------------------------------------------------------------------------
// Scan pass 1: compose 64 affine steps per (b, chunk, h) into (A, B).
// ---------------------------------------------------------------------------
__global__ __launch_bounds__(256)
void mingru_scan_pass1(void)
{
    const int idx = blockIdx.x * blockDim.x + threadIdx.x;
    const int h = idx & (HH - 1);
    const int c = (idx >> 8) & (NCH - 1);
    const int b = idx >> 14;

    const size_t base = ((size_t)b * TT + (size_t)c * CLEN) * HH + h;
    const float* __restrict__ gp = g_scratch + base;
    const float* __restrict__ up = u_scratch + base;

    float A = 1.0f, Bv = 0.0f;
#pragma unroll 8
    for (int t = 0; t < CLEN; t++) {
        const size_t off = (size_t)t * HH;
        float g = gp[off];
        float u = up[off];
        float a = 1.0f - g;
        Bv = fmaf(a, Bv, g * u);
        A  = A * a;
    }
    chunkA[idx] = A;
    chunkB[idx] = Bv;
}

// ---------------------------------------------------------------------------
// Scan pass 2: carry h0 across chunk summaries; store chunk-start states.
// ---------------------------------------------------------------------------
__global__ __launch_bounds__(256)
void mingru_scan_pass2(const float* __restrict__ h0)
{
    const int idx = blockIdx.x * blockDim.x + threadIdx.x;  // 0..2047
    const int h = idx & (HH - 1);
    const int b = idx >> 8;

    float hc = h0[b * HH + h];
#pragma unroll 8
    for (int c = 0; c < NCH; c++) {
        const size_t ci = ((size_t)b * NCH + c) * HH + h;
        hstart[ci] = hc;
        hc = fmaf(chunkA[ci], hc, chunkB[ci]);
    }
}

// ---------------------------------------------------------------------------
// Scan pass 3: replay each chunk from its start state, write outputs.
// ---------------------------------------------------------------------------
__global__ __launch_bounds__(256)
void mingru_scan_pass3(float* __restrict__ out)
{
    const int idx = blockIdx.x * blockDim.x + threadIdx.x;
    const int h = idx & (HH - 1);
    const int c = (idx >> 8) & (NCH - 1);
    const int b = idx >> 14;

    const size_t base = ((size_t)b * TT + (size_t)c * CLEN) * HH + h;
    const float* __restrict__ gp = g_scratch + base;
    const float* __restrict__ up = u_scratch + base;
    float* __restrict__ op = out + base;

    float hc = hstart[idx];
#pragma unroll 8
    for (int t = 0; t < CLEN; t++) {
        const size_t off = (size_t)t * HH;
        float g = gp[off];
        float u = up[off];
        hc = fmaf(g, u - hc, hc);
        op[off] = hc;
    }
}

extern "C" void kernel_launch(void* const* d_in, const int* in_sizes, int n_in,
                              void* d_out, int out_size)
{
    const float* x  = (const float*)d_in[0];   // [B,T,D]
    const float* h0 = (const float*)d_in[1];   // [B,H]
    const float* Wz = (const float*)d_in[2];   // [H,D]
    const float* bz = (const float*)d_in[3];   // [H]
    const float* Wh = (const float*)d_in[4];   // [H,D]
    const float* bh = (const float*)d_in[5];   // [H]
    float* out = (float*)d_out;                // [B,T,H]

    cudaFuncSetAttribute(mingru_gemm_tc,
                         cudaFuncAttributeMaxDynamicSharedMemorySize, GEMM_SMEM);

    mingru_wprep_kernel<<<NN * DD / 256, 256>>>(Wz, Wh);

    dim3 grid(2, MM / 128);
    mingru_gemm_tc<<<grid, 128, GEMM_SMEM>>>(x, bz, bh);

    const int scan_threads = BB * NCH * HH;    // 131072
    mingru_scan_pass1<<<scan_threads / 256, 256>>>();
    mingru_scan_pass2<<<BB * HH / 256, 256>>>(h0);
    mingru_scan_pass3<<<scan_threads / 256, 256>>>(out);
}

// round 6
// speedup vs baseline: 7.7302x; 2.3086x over previous
#include <cuda_runtime.h>
#include <cuda_bf16.h>
#include <math.h>
#include <stdint.h>

// Problem constants (MinGRUCell: B=8, T=4096, D=256, H=256)
#define BB 8
#define TT 4096
#define DD 256
#define HH 256
#define MM (BB * TT)          // 32768 rows
#define NN 512                // logical N: gate(256) + update(256)

// Chunked scan config
#define NCH 128
#define CLEN 32               // NCH*CLEN == TT

// tcgen05 only exists in the arch-specific compilation pass.
#if defined(__CUDA_ARCH_FEAT_SM103_ALL) || defined(__CUDA_ARCH_FEAT_SM100_ALL) || defined(__CUDA_ARCH_FEAT_SM101_ALL)
#define HAS_TCGEN05 1
#else
#define HAS_TCGEN05 0
#endif

// Scratch
__device__ float g_scratch[(size_t)MM * HH];
__device__ float u_scratch[(size_t)MM * HH];
__device__ float chunkA[(size_t)BB * NCH * HH];
__device__ float chunkB[(size_t)BB * NCH * HH];
__device__ float hstart[(size_t)BB * NCH * HH];
// Pre-split weights: rows 0..255 = Wz, 256..511 = Wh   [NN, DD] bf16
__device__ __nv_bfloat16 Wcat_hi[(size_t)NN * DD];
__device__ __nv_bfloat16 Wcat_lo[(size_t)NN * DD];
// Pre-split activations [MM, DD] bf16
__device__ __nv_bfloat16 x_hi[(size_t)MM * DD];
__device__ __nv_bfloat16 x_lo[(size_t)MM * DD];

// ---------------------------------------------------------------------------
// PTX helpers
// ---------------------------------------------------------------------------
__device__ __forceinline__ uint32_t smem_u32(const void* p) {
    uint32_t a;
    asm("{ .reg .u64 t; cvta.to.shared.u64 t, %1; cvt.u32.u64 %0, t; }"
        : "=r"(a) : "l"(p));
    return a;
}

#define SW128(o) ((o) ^ (((o) >> 3) & 0x70))

static constexpr uint64_t SMEM_DESC_BASE_SW128_C =
    (uint64_t(2)  << 61) | (uint64_t(1) << 46) | (uint64_t(64) << 32) | (uint64_t(1) << 16);
#define MK_DESC(addr) (SMEM_DESC_BASE_SW128_C | ((uint64_t)((addr) >> 4) & 0x3FFF))

#define CP_ASYNC16(dst, src) \
    asm volatile("cp.async.cg.shared.global [%0], [%1], 16;" :: "r"(dst), "l"(src) : "memory")
#define CP_COMMIT()  asm volatile("cp.async.commit_group;" ::: "memory")
#define CP_WAIT0()   asm volatile("cp.async.wait_group 0;" ::: "memory")

#if HAS_TCGEN05
#define TC_ALLOC(sm, n)  asm volatile("tcgen05.alloc.cta_group::1.sync.aligned.shared::cta.b32 [%0], %1;" :: "r"((uint32_t)(sm)), "r"((uint32_t)(n)) : "memory")
#define TC_DEALLOC(t, n) asm volatile("tcgen05.dealloc.cta_group::1.sync.aligned.b32 %0, %1;" :: "r"(t), "r"((uint32_t)(n)))
#define TC_RELINQ()      asm volatile("tcgen05.relinquish_alloc_permit.cta_group::1.sync.aligned;")
#define TC_COMMIT(mb)    asm volatile("tcgen05.commit.cta_group::1.mbarrier::arrive::one.shared::cluster.b64 [%0];" :: "r"((uint32_t)(mb)) : "memory")
#define TC_WAIT_LD()     asm volatile("tcgen05.wait::ld.sync.aligned;" ::: "memory")
#define TC_FENCE_AFTER() asm volatile("tcgen05.fence::after_thread_sync;" ::: "memory")
#define TC_FENCE_BEFORE() asm volatile("tcgen05.fence::before_thread_sync;" ::: "memory")
#define FENCE_ASYNC()    asm volatile("fence.proxy.async.shared::cta;" ::: "memory")
#define MBAR_INIT(mb, c) asm volatile("mbarrier.init.shared.b64 [%0], %1;" :: "r"((uint32_t)(mb)), "r"((uint32_t)(c)) : "memory")

#define MBAR_WAIT(mb, ph) do {                                                 \
    uint32_t _m = (uint32_t)(mb), _p = (uint32_t)(ph), _d;                     \
    asm volatile("{\n\t.reg .pred p;\n\t"                                      \
        "mbarrier.try_wait.parity.acquire.cta.shared::cta.b64 p, [%1], %2;\n\t"\
        "selp.b32 %0, 1, 0, p;\n\t}"                                           \
        : "=r"(_d) : "r"(_m), "r"(_p) : "memory");                             \
    if (!_d) {                                                                 \
        asm volatile("{\n\t.reg .pred P1;\n\t"                                 \
            "WL_%=:\n\t"                                                       \
            "mbarrier.try_wait.parity.acquire.cta.shared::cta.b64 P1, [%0], %1, 0x989680;\n\t" \
            "@P1 bra.uni WD_%=;\n\t"                                           \
            "bra.uni WL_%=;\n\t"                                               \
            "WD_%=:\n\t}"                                                      \
            :: "r"(_m), "r"(_p) : "memory");                                   \
    }                                                                          \
} while (0)

#define LDTM32(r, ta)                                                          \
    asm volatile("tcgen05.ld.sync.aligned.32x32b.x32.b32 "                     \
        "{%0,%1,%2,%3,%4,%5,%6,%7,%8,%9,%10,%11,%12,%13,%14,%15,"              \
        "%16,%17,%18,%19,%20,%21,%22,%23,%24,%25,%26,%27,%28,%29,%30,%31}, [%32];" \
        : "=r"((r)[0]),"=r"((r)[1]),"=r"((r)[2]),"=r"((r)[3]),                 \
          "=r"((r)[4]),"=r"((r)[5]),"=r"((r)[6]),"=r"((r)[7]),                 \
          "=r"((r)[8]),"=r"((r)[9]),"=r"((r)[10]),"=r"((r)[11]),               \
          "=r"((r)[12]),"=r"((r)[13]),"=r"((r)[14]),"=r"((r)[15]),             \
          "=r"((r)[16]),"=r"((r)[17]),"=r"((r)[18]),"=r"((r)[19]),             \
          "=r"((r)[20]),"=r"((r)[21]),"=r"((r)[22]),"=r"((r)[23]),             \
          "=r"((r)[24]),"=r"((r)[25]),"=r"((r)[26]),"=r"((r)[27]),             \
          "=r"((r)[28]),"=r"((r)[29]),"=r"((r)[30]),"=r"((r)[31])              \
        : "r"(ta))

__device__ __forceinline__ void mma_f16_ss(uint32_t d, uint64_t a, uint64_t b,
                                           uint32_t idesc, uint32_t en) {
    asm volatile(
        "{\n\t.reg .pred p;\n\tsetp.ne.u32 p, %5, 0;\n\t"
        "tcgen05.mma.cta_group::1.kind::f16 [%0], %1, %2, %3, {%4, %4, %4, %4}, p;\n\t}"
        :: "r"(d), "l"(a), "l"(b), "r"(idesc), "r"(0u), "r"(en) : "memory");
}
#endif // HAS_TCGEN05

// idesc: dtype=F32, atype=BF16, btype=BF16, N=256, M=128
static constexpr uint32_t GEMM_IDESC =
    (1u << 4) | (1u << 7) | (1u << 10) | ((256u / 8) << 17) | ((128u / 16) << 24);

// ---------------------------------------------------------------------------
// Weight pre-split
// ---------------------------------------------------------------------------
__global__ __launch_bounds__(256)
void mingru_wprep_kernel(const float* __restrict__ Wz, const float* __restrict__ Wh)
{
    const int i = blockIdx.x * 256 + threadIdx.x;
    const int n = i >> 8;
    const int d = i & 255;
    float v = (n < HH) ? Wz[n * DD + d] : Wh[(n - HH) * DD + d];
    __nv_bfloat16 hi = __float2bfloat16(v);
    Wcat_hi[i] = hi;
    Wcat_lo[i] = __float2bfloat16(v - __bfloat162float(hi));
}

// ---------------------------------------------------------------------------
// Activation pre-split: x fp32 -> x_hi, x_lo bf16 (one float4 per thread)
// ---------------------------------------------------------------------------
__global__ __launch_bounds__(256)
void mingru_xsplit_kernel(const float* __restrict__ x)
{
    const size_t i4 = (size_t)blockIdx.x * 256 + threadIdx.x;
    float4 v = reinterpret_cast<const float4*>(x)[i4];
    __nv_bfloat16 h0 = __float2bfloat16(v.x);
    __nv_bfloat16 h1 = __float2bfloat16(v.y);
    __nv_bfloat16 h2 = __float2bfloat16(v.z);
    __nv_bfloat16 h3 = __float2bfloat16(v.w);
    __nv_bfloat162 hp0(h0, h1), hp1(h2, h3);
    __nv_bfloat162 lp0(__float2bfloat16(v.x - __bfloat162float(h0)),
                       __float2bfloat16(v.y - __bfloat162float(h1)));
    __nv_bfloat162 lp1(__float2bfloat16(v.z - __bfloat162float(h2)),
                       __float2bfloat16(v.w - __bfloat162float(h3)));
    uint2 hw = make_uint2(*(uint32_t*)&hp0, *(uint32_t*)&hp1);
    uint2 lw = make_uint2(*(uint32_t*)&lp0, *(uint32_t*)&lp1);
    reinterpret_cast<uint2*>(x_hi)[i4] = hw;
    reinterpret_cast<uint2*>(x_lo)[i4] = lw;
}

// ---------------------------------------------------------------------------
// Pipelined tcgen05 GEMM. CTA: M=128, N=256 (gate or update), K=256 in
// 4 chunks of 64. 2-stage cp.async double buffering; pure 16B copies.
// grid = (2, 256), 256 threads, 1 CTA/SM.
// Stage buffers MUST be 1024-byte aligned (SW128 atom) — header ends at 2048.
// ---------------------------------------------------------------------------
#define KCH 64
#define NKC (DD / KCH)          // 4
// header: [0..4) tmem ptr, [8..16) mbar, [16..1040) bias (256 f32)
#define HDR_BIAS 16
#define STAGE0_OFF 2048
#define STAGE_BYTES (96 * 1024)
#define ST_A_HI 0
#define ST_A_LO (16 * 1024)
#define ST_B_HI (32 * 1024)
#define ST_B_LO (64 * 1024)
#define GEMM_SMEM (STAGE0_OFF + 2 * STAGE_BYTES + 1024)

__global__ __launch_bounds__(256, 1)
void mingru_gemm_tc(const float* __restrict__ bz,
                    const float* __restrict__ bh)
{
#if HAS_TCGEN05
    extern __shared__ char smem_raw[];
    char* smem = (char*)(((uintptr_t)smem_raw + 1023) & ~(uintptr_t)1023);
    const uint32_t sbase = smem_u32(smem);

    const int tid = threadIdx.x;            // 0..255
    const int m0 = blockIdx.y * 128;
    const bool is_gate = (blockIdx.x == 0);
    const int n0 = blockIdx.x * 256;        // row offset into Wcat
    const float* __restrict__ bias = is_gate ? bz : bh;
    float* __restrict__ outbuf = is_gate ? g_scratch : u_scratch;

    if (tid < 32) TC_ALLOC(sbase + 0, 256);
    if (tid == 0) MBAR_INIT(sbase + 8, 1);
    // bias into smem
    *reinterpret_cast<float*>(smem + HDR_BIAS + tid * 4) = bias[tid];
    __syncthreads();
    uint32_t tmem;
    asm volatile("ld.shared.b32 %0, [%1];" : "=r"(tmem) : "r"(sbase + 0));

    // ---- stage loader: 24 cp.async x 16B per thread ----
    auto load_stage = [&](int s, int kc) {
        const uint32_t st = sbase + STAGE0_OFF + s * STAGE_BYTES;
        const int k0 = kc * KCH;
        // A_hi + A_lo: 128 rows x 8 x 16B each
#pragma unroll
        for (int j = 0; j < 4; j++) {
            const int i = j * 256 + tid;         // 0..1023
            const int row = i >> 3;
            const int c16 = i & 7;
            const uint32_t off = SW128((uint32_t)(row * 128 + c16 * 16));
            const size_t src = (size_t)(m0 + row) * DD + k0 + c16 * 8;
            CP_ASYNC16(st + ST_A_HI + off, (const char*)&x_hi[src]);
            CP_ASYNC16(st + ST_A_LO + off, (const char*)&x_lo[src]);
        }
        // B_hi + B_lo: 256 rows x 8 x 16B each
#pragma unroll
        for (int j = 0; j < 8; j++) {
            const int i = j * 256 + tid;         // 0..2047
            const int row = i >> 3;
            const int c16 = i & 7;
            const uint32_t off = SW128((uint32_t)(row * 128 + c16 * 16));
            const size_t src = (size_t)(n0 + row) * DD + k0 + c16 * 8;
            CP_ASYNC16(st + ST_B_HI + off, (const char*)&Wcat_hi[src]);
            CP_ASYNC16(st + ST_B_LO + off, (const char*)&Wcat_lo[src]);
        }
        CP_COMMIT();
    };

    load_stage(0, 0);

    for (int kc = 0; kc < NKC; kc++) {
        const int s = kc & 1;
        CP_WAIT0();             // stage kc loads complete
        __syncthreads();

        if (tid == 0) {
            FENCE_ASYNC();
            const uint32_t st = sbase + STAGE0_OFF + s * STAGE_BYTES;
            const uint64_t ahi = MK_DESC(st + ST_A_HI);
            const uint64_t alo = MK_DESC(st + ST_A_LO);
            const uint64_t bhi = MK_DESC(st + ST_B_HI);
            const uint64_t blo = MK_DESC(st + ST_B_LO);
            const uint64_t ad[3] = { ahi, alo, ahi };
            const uint64_t bd[3] = { bhi, bhi, blo };
#pragma unroll
            for (int p = 0; p < 3; p++)
#pragma unroll
                for (int ks = 0; ks < 4; ks++)
                    mma_f16_ss(tmem, ad[p] + ks * 2, bd[p] + ks * 2,
                               GEMM_IDESC, (kc > 0 || p > 0 || ks > 0) ? 1u : 0u);
            TC_COMMIT(sbase + 8);
        }
        if (kc >= 1) MBAR_WAIT(sbase + 8, (kc - 1) & 1);  // MMA(kc-1) done -> buffer free
        if (kc + 1 < NKC) load_stage(s ^ 1, kc + 1);
    }
    MBAR_WAIT(sbase + 8, (NKC - 1) & 1);   // MMA(last) done
    TC_FENCE_AFTER();

    // ---- Epilogue: warp w -> rows (w&3)*32+lane, cols (w>>2)*128 .. +128 ----
    {
        const int w = tid >> 5;
        const int lane = tid & 31;
        const int row = (w & 3) * 32 + lane;
        const int colbase = (w >> 2) * 128;
        float* __restrict__ orow = outbuf + (size_t)(m0 + row) * HH;
        const float* __restrict__ bias_s = reinterpret_cast<const float*>(smem + HDR_BIAS);
#pragma unroll
        for (int half = 0; half < 2; half++) {
            const int cb = colbase + half * 64;
            uint32_t r[64];
            LDTM32(r, tmem + cb);
            LDTM32(r + 32, tmem + cb + 32);
            TC_WAIT_LD();
#pragma unroll
            for (int q = 0; q < 16; q++) {
                float4 v;
                v.x = __uint_as_float(r[q * 4 + 0]) + bias_s[cb + q * 4 + 0];
                v.y = __uint_as_float(r[q * 4 + 1]) + bias_s[cb + q * 4 + 1];
                v.z = __uint_as_float(r[q * 4 + 2]) + bias_s[cb + q * 4 + 2];
                v.w = __uint_as_float(r[q * 4 + 3]) + bias_s[cb + q * 4 + 3];
                if (is_gate) {
                    v.x = 1.0f / (1.0f + __expf(-v.x));
                    v.y = 1.0f / (1.0f + __expf(-v.y));
                    v.z = 1.0f / (1.0f + __expf(-v.z));
                    v.w = 1.0f / (1.0f + __expf(-v.w));
                }
                *reinterpret_cast<float4*>(&orow[cb + q * 4]) = v;
            }
        }
    }

    __syncthreads();
    if (tid < 32) {
        TC_RELINQ();
        TC_DEALLOC(tmem, 256);
    }
#endif // HAS_TCGEN05
}

// ---------------------------------------------------------------------------
// Scan pass 1: compose CLEN affine steps per (b, chunk, h) into (A, B).
// ---------------------------------------------------------------------------
__global__ __launch_bounds__(256)
void mingru_scan_pass1(void)
{
    const int idx = blockIdx.x * blockDim.x + threadIdx.x;
    const int h = idx & (HH - 1);
    const int c = (idx >> 8) & (NCH - 1);
    const int b = idx >> 15;

    const size_t base = ((size_t)b * TT + (size_t)c * CLEN) * HH + h;
    const float* __restrict__ gp = g_scratch + base;
    const float* __restrict__ up = u_scratch + base;

    float A = 1.0f, Bv = 0.0f;
#pragma unroll 8
    for (int t = 0; t < CLEN; t++) {
        const size_t off = (size_t)t * HH;
        float g = gp[off];
        float u = up[off];
        float a = 1.0f - g;
        Bv = fmaf(a, Bv, g * u);
        A  = A * a;
    }
    chunkA[idx] = A;
    chunkB[idx] = Bv;
}

// ---------------------------------------------------------------------------
// Scan pass 2: carry h0 across chunk summaries with 8-wide load batching.
// ---------------------------------------------------------------------------
__global__ __launch_bounds__(256)
void mingru_scan_pass2(const float* __restrict__ h0)
{
    const int idx = blockIdx.x * blockDim.x + threadIdx.x;  // 0..2047
    const int h = idx & (HH - 1);
    const int b = idx >> 8;

    float hc = h0[b * HH + h];
    const size_t cb0 = (size_t)b * NCH * HH + h;
    for (int c0 = 0; c0 < NCH; c0 += 8) {
        float a[8], bb[8];
#pragma unroll
        for (int j = 0; j < 8; j++) {
            const size_t ci = cb0 + (size_t)(c0 + j) * HH;
            a[j]  = chunkA[ci];
            bb[j] = chunkB[ci];
        }
#pragma unroll
        for (int j = 0; j < 8; j++) {
            const size_t ci = cb0 + (size_t)(c0 + j) * HH;
            hstart[ci] = hc;
            hc = fmaf(a[j], hc, bb[j]);
        }
    }
}

// ---------------------------------------------------------------------------
// Scan pass 3: replay each chunk from its start state, write outputs.
// ---------------------------------------------------------------------------
__global__ __launch_bounds__(256)
void mingru_scan_pass3(float* __restrict__ out)
{
    const int idx = blockIdx.x * blockDim.x + threadIdx.x;
    const int h = idx & (HH - 1);
    const int c = (idx >> 8) & (NCH - 1);
    const int b = idx >> 15;

    const size_t base = ((size_t)b * TT + (size_t)c * CLEN) * HH + h;
    const float* __restrict__ gp = g_scratch + base;
    const float* __restrict__ up = u_scratch + base;
    float* __restrict__ op = out + base;

    float hc = hstart[idx];
#pragma unroll 8
    for (int t = 0; t < CLEN; t++) {
        const size_t off = (size_t)t * HH;
        float g = gp[off];
        float u = up[off];
        hc = fmaf(g, u - hc, hc);
        op[off] = hc;
    }
}

extern "C" void kernel_launch(void* const* d_in, const int* in_sizes, int n_in,
                              void* d_out, int out_size)
{
    const float* x  = (const float*)d_in[0];   // [B,T,D]
    const float* h0 = (const float*)d_in[1];   // [B,H]
    const float* Wz = (const float*)d_in[2];   // [H,D]
    const float* bz = (const float*)d_in[3];   // [H]
    const float* Wh = (const float*)d_in[4];   // [H,D]
    const float* bh = (const float*)d_in[5];   // [H]
    float* out = (float*)d_out;                // [B,T,H]

    cudaFuncSetAttribute(mingru_gemm_tc,
                         cudaFuncAttributeMaxDynamicSharedMemorySize, GEMM_SMEM);

    mingru_wprep_kernel<<<NN * DD / 256, 256>>>(Wz, Wh);
    mingru_xsplit_kernel<<<MM * DD / 4 / 256, 256>>>(x);

    dim3 grid(2, MM / 128);
    mingru_gemm_tc<<<grid, 256, GEMM_SMEM>>>(bz, bh);

    const int scan_threads = BB * NCH * HH;    // 262144
    mingru_scan_pass1<<<scan_threads / 256, 256>>>();
    mingru_scan_pass2<<<BB * HH / 256, 256>>>(h0);
    mingru_scan_pass3<<<scan_threads / 256, 256>>>(out);
}